// round 16
// baseline (speedup 1.0000x reference)
#include <cuda_runtime.h>
#include <cuda_fp16.h>
#include <math.h>
#include <stdint.h>

// ---------------------------------------------------------------------------
// HaplotypeEmbedding, fp16 + mma.sync m16n8k16 + ldmatrix.
// convert_kernel + gemm_p_kernel prolog (r12 winner, unchanged).
// main_kernel: MTILE 128 @ 512 threads, occ 1 (16 warps/SM, same warp tile
// 32x64, same pipeline) -- halves W2-tile staging traffic per sample.
// ---------------------------------------------------------------------------

#define L_    8
#define V_    512
#define D_    256
#define HID_  512
#define NOUT_ 256
#define NTOT  131072
#define KCH   64
#define NCH   (HID_ / KCH)     // 8

#define SAH 72
#define SBH 72

// ---- gemm_p (MTILE 64) smem layout ----
#define SA_BUFH (64 * SAH)      // 4608 halves
#define SB_BUFH (NOUT_ * SBH)   // 18432 halves
#define SM_A_B   2048
#define SM_B_B   (SM_A_B + 2 * SA_BUFH * 2)     // 20480
#define SMEM_BYTES (SM_B_B + 2 * SB_BUFH * 2)   // 94208

// ---- main (MTILE 128) smem layout ----
#define MTILE 128
#define NBLK  (NTOT / MTILE)    // 1024
#define MSA_BUFH (MTILE * SAH)  // 9216 halves
#define MSM_TOK_B 0
#define MSM_A_B   4096
#define MSM_B_B   (MSM_A_B + 2 * MSA_BUFH * 2)      // 40960
#define MSMEM_BYTES (MSM_B_B + 2 * SB_BUFH * 2)     // 114688

__device__ __half g_Ph[L_ * V_ * HID_];      // P (+b1/8), fp16
__device__ __half g_W2T[NOUT_ * HID_];       // W2^T fp16 [n][k]
__device__ __half g_W1T[HID_ * (L_ * D_)];   // W1^T fp16 [j][d]
__device__ int    g_is64;

__device__ __forceinline__ float gelu_fast(float x) {
    float ax = fabsf(x);
    float z  = 0.70710678118f * ax;
    float t  = __fdividef(1.0f, fmaf(0.47047f, z, 1.0f));
    float q  = fmaf(fmaf(0.7478556f, t, -0.0958798f), t, 0.3480242f) * t;
    float e  = __expf(-z * z);
    float er = fmaf(-q, e, 1.0f);
    return fmaf(0.5f * ax, er, 0.5f * x);
}
__device__ __forceinline__ void mma_f16(float* d, const uint32_t* a,
                                        uint32_t b0, uint32_t b1) {
    asm volatile(
        "mma.sync.aligned.m16n8k16.row.col.f32.f16.f16.f32 "
        "{%0,%1,%2,%3}, {%4,%5,%6,%7}, {%8,%9}, {%0,%1,%2,%3};"
        : "+f"(d[0]), "+f"(d[1]), "+f"(d[2]), "+f"(d[3])
        : "r"(a[0]), "r"(a[1]), "r"(a[2]), "r"(a[3]), "r"(b0), "r"(b1));
}
__device__ __forceinline__ void ldsm4(uint32_t& r0, uint32_t& r1,
                                      uint32_t& r2, uint32_t& r3, uint32_t a) {
    asm volatile("ldmatrix.sync.aligned.m8n8.x4.shared.b16 {%0,%1,%2,%3}, [%4];"
                 : "=r"(r0), "=r"(r1), "=r"(r2), "=r"(r3) : "r"(a));
}
__device__ __forceinline__ void cpasync16(uint32_t dst, const void* src) {
    asm volatile("cp.async.ca.shared.global [%0], [%1], 16;"
                 :: "r"(dst), "l"(src) : "memory");
}

// ---------------------------------------------------------------------------
__global__ void __launch_bounds__(256) convert_kernel(
        const float* __restrict__ W1, const float* __restrict__ W2,
        const unsigned int* __restrict__ hap) {
    __shared__ float sT[64 * 68];
    const int t = threadIdx.x;
    const int bx = blockIdx.x;

    if (bx == 0 && t == 0) {
        int ok = 1;
        for (int i = 0; i < 64; i++) ok &= (hap[2 * i + 1] == 0u);
        g_is64 = ok;
    }

    const float* src; __half* dst;
    int d0, j0, S, Dst;
    if (bx < 256) {
        d0 = (bx >> 3) * 64; j0 = (bx & 7) * 64;
        S = HID_; Dst = L_ * D_;
        src = W1; dst = g_W1T;
    } else {
        int i2 = bx - 256;
        d0 = (i2 >> 2) * 64; j0 = (i2 & 3) * 64;
        S = NOUT_; Dst = HID_;
        src = W2; dst = g_W2T;
    }

    const int rr = t >> 2, q = t & 3;
    const float* sp = src + (size_t)(d0 + rr) * S + j0 + q * 16;
#pragma unroll
    for (int i = 0; i < 4; i++)
        *(float4*)(sT + rr * 68 + q * 16 + i * 4) = *(const float4*)(sp + i * 4);
    __syncthreads();

    const int jj = t >> 2, qq = t & 3;
    __half h[16];
#pragma unroll
    for (int i = 0; i < 16; i++)
        h[i] = __float2half_rn(sT[(qq * 16 + i) * 68 + jj]);
    __half* dp = dst + (size_t)(j0 + jj) * Dst + d0 + qq * 16;
    *(uint4*)(dp)     = *(uint4*)(h);
    *(uint4*)(dp + 8) = *(uint4*)(h + 8);
}

// ---------------------------------------------------------------------------
__global__ void __launch_bounds__(256, 2) gemm_p_kernel(
        const float* __restrict__ tables,
        const float* __restrict__ b1) {
    extern __shared__ char smem[];
    __half* sA = (__half*)(smem + SM_A_B);
    __half* sB = (__half*)(smem + SM_B_B);
    const uint32_t sbA = (uint32_t)__cvta_generic_to_shared(sA);
    const uint32_t sbB = (uint32_t)__cvta_generic_to_shared(sB);

    const int tid = threadIdx.x, warp = tid >> 5, lane = tid & 31;
    const int l   = blockIdx.x >> 4;
    const int mv  = (blockIdx.x >> 1) & 7;
    const int nt  = blockIdx.x & 1;
    const int v0  = mv * 64;

    float acc[2][8][4];
#pragma unroll
    for (int mt = 0; mt < 2; mt++)
#pragma unroll
        for (int j = 0; j < 8; j++)
#pragma unroll
            for (int q = 0; q < 4; q++) acc[mt][j][q] = 0.f;

    const int m0 = (warp >> 2) * 32;
    const int n0 = (warp & 3) * 64;
    const int bn = tid >> 3;
    const int bc = tid & 7;
    const int ar = tid >> 2;
    const int aq = tid & 3;

    const uint32_t aoff0 = ((uint32_t)(m0 + ((lane >> 3) & 1) * 8 + (lane & 7)) * SAH +
                            (uint32_t)(lane >> 4) * 8) * 2;
    const uint32_t boff0 = ((uint32_t)(n0 + (lane >> 4) * 8 + (lane & 7)) * SBH +
                            (uint32_t)((lane >> 3) & 1) * 8) * 2;

    const float* Asrc = tables + (size_t)(l * V_ + v0 + ar) * D_ + aq * 16;
    const __half* Bsrc = g_W1T + (size_t)(nt * NOUT_) * (L_ * D_) + l * D_ + bc * 8;

    auto produce = [&](int kt, int buf) {
        {
            const uint32_t dstB = sbB + (uint32_t)(buf * SB_BUFH * 2);
#pragma unroll
            for (int i = 0; i < 8; i++) {
                int n = bn + i * 32;
                cpasync16(dstB + (uint32_t)(n * SBH + bc * 8) * 2,
                          Bsrc + (size_t)n * (L_ * D_) + kt * KCH);
            }
            asm volatile("cp.async.commit_group;" ::: "memory");
        }
        {
            const float* ap = Asrc + kt * KCH;
            __half h[16];
#pragma unroll
            for (int i = 0; i < 4; i++) {
                float4 v = *(const float4*)(ap + i * 4);
                h[4 * i + 0] = __float2half_rn(v.x);
                h[4 * i + 1] = __float2half_rn(v.y);
                h[4 * i + 2] = __float2half_rn(v.z);
                h[4 * i + 3] = __float2half_rn(v.w);
            }
            __half* A = sA + buf * SA_BUFH + ar * SAH + aq * 16;
            *(uint4*)(A)     = *(uint4*)(h);
            *(uint4*)(A + 8) = *(uint4*)(h + 8);
        }
    };

    auto consume = [&](int buf) {
        const uint32_t aB = sbA + (uint32_t)(buf * SA_BUFH * 2) + aoff0;
        const uint32_t bB = sbB + (uint32_t)(buf * SB_BUFH * 2) + boff0;
#pragma unroll
        for (int ks = 0; ks < 4; ks++) {
            uint32_t a[2][4];
#pragma unroll
            for (int mt = 0; mt < 2; mt++)
                ldsm4(a[mt][0], a[mt][1], a[mt][2], a[mt][3],
                      aB + (uint32_t)(mt * 16 * SAH * 2) + (uint32_t)(ks * 32));
#pragma unroll
            for (int jp = 0; jp < 4; jp++) {
                uint32_t b0, b1r, b2r, b3r;
                ldsm4(b0, b1r, b2r, b3r,
                      bB + (uint32_t)(jp * 16 * SBH * 2) + (uint32_t)(ks * 32));
                mma_f16(acc[0][2 * jp],     a[0], b0, b1r);
                mma_f16(acc[1][2 * jp],     a[1], b0, b1r);
                mma_f16(acc[0][2 * jp + 1], a[0], b2r, b3r);
                mma_f16(acc[1][2 * jp + 1], a[1], b2r, b3r);
            }
        }
    };

    produce(0, 0);
    asm volatile("cp.async.wait_group 0;" ::: "memory");
    __syncthreads();
#pragma unroll 1
    for (int kt = 0; kt < 4; kt++) {
        const int buf = kt & 1;
        if (kt + 1 < 4) produce(kt + 1, buf ^ 1);
        consume(buf);
        asm volatile("cp.async.wait_group 0;" ::: "memory");
        __syncthreads();
    }

    const float2* b1p = (const float2*)b1;
#pragma unroll
    for (int mt = 0; mt < 2; mt++) {
        int r0 = v0 + m0 + mt * 16 + (lane >> 2);
#pragma unroll
        for (int j = 0; j < 8; j++) {
            int cc = n0 / 2 + 4 * j + (lane & 3);
            int jcol = nt * NOUT_ + 2 * cc;
            float2 bv = __ldg(&b1p[jcol >> 1]);
            bv.x *= 0.125f; bv.y *= 0.125f;
            __half2 h0 = __floats2half2_rn(acc[mt][j][0] + bv.x,
                                           acc[mt][j][1] + bv.y);
            __half2 h1 = __floats2half2_rn(acc[mt][j][2] + bv.x,
                                           acc[mt][j][3] + bv.y);
            *(uint32_t*)(g_Ph + (size_t)(l * V_ + r0) * HID_ + jcol) =
                *(uint32_t*)&h0;
            *(uint32_t*)(g_Ph + (size_t)(l * V_ + r0 + 8) * HID_ + jcol) =
                *(uint32_t*)&h1;
        }
    }
}

// ---------------------------------------------------------------------------
__global__ void __launch_bounds__(512, 1) main_kernel(
        const unsigned int* __restrict__ hap,
        const float* __restrict__ b2,
        float* __restrict__ out) {
    extern __shared__ char smem[];
    int*    sTok = (int*)(smem + MSM_TOK_B);
    __half* sA   = (__half*)(smem + MSM_A_B);
    __half* sB   = (__half*)(smem + MSM_B_B);
    const uint32_t sbA = (uint32_t)__cvta_generic_to_shared(sA);
    const uint32_t sbB = (uint32_t)__cvta_generic_to_shared(sB);

    const int tid = threadIdx.x, warp = tid >> 5, lane = tid & 31;
    const int is64 = g_is64;

    // tokens (clamped): 1024 per block, 2 per thread
    {
        long gbase = (long)blockIdx.x * (MTILE * L_);
#pragma unroll
        for (int i = 0; i < 2; i++) {
            int idx = tid + 512 * i;
            long gi = gbase + idx;
            int v = is64 ? (int)hap[2 * gi] : (int)hap[gi];
            v = v < 0 ? 0 : (v > V_ - 1 ? V_ - 1 : v);
            sTok[idx] = v;
        }
    }

    float acc[2][8][4];
#pragma unroll
    for (int mt = 0; mt < 2; mt++)
#pragma unroll
        for (int j = 0; j < 8; j++)
#pragma unroll
            for (int q = 0; q < 4; q++) acc[mt][j][q] = 0.f;

    const int c  = lane & 7;            // 16B segment (producer)
    const int r  = lane >> 3;           // row sub-index (producer)
    const int m0 = (warp >> 2) * 32;    // consumer row base (0/32/64/96)
    const int n0 = (warp & 3) * 64;     // consumer col base
    const int bn = tid >> 3;            // B-stage row (0..63)
    const int bc = tid & 7;

    const uint32_t aoff0 = ((uint32_t)(m0 + ((lane >> 3) & 1) * 8 + (lane & 7)) * SAH +
                            (uint32_t)(lane >> 4) * 8) * 2;
    const uint32_t boff0 = ((uint32_t)(n0 + (lane >> 4) * 8 + (lane & 7)) * SBH +
                            (uint32_t)((lane >> 3) & 1) * 8) * 2;

    __syncthreads();

    uint4 u[8];   // gathered 16B segments for one it-half

    auto stageB = [&](int kt, int buf) {
        const uint32_t dstB = sbB + (uint32_t)(buf * SB_BUFH * 2);
        const __half* srcB = g_W2T + kt * KCH + bc * 8;
#pragma unroll
        for (int i = 0; i < 4; i++) {
            int n = bn + i * 64;
            cpasync16(dstB + (uint32_t)(n * SBH + bc * 8) * 2,
                      srcB + n * HID_);
        }
        asm volatile("cp.async.commit_group;" ::: "memory");
    };

    auto loadA = [&](int it, int kt) {
        const int k0 = kt * KCH;
        const int m = it * 64 + warp * 4 + r;
        const int* tk = sTok + m * L_;
#pragma unroll
        for (int lp = 0; lp < 8; lp++)
            u[lp] = *(const uint4*)(g_Ph +
                    ((lp * V_ + tk[lp]) << 9) + k0 + c * 8);
    };

    auto mathA = [&](int it, int buf) {
        float2 a0 = make_float2(0.f, 0.f), a1 = a0, a2 = a0, a3 = a0;
#pragma unroll
        for (int lp = 0; lp < 4; lp++) {
            __half2 t; float2 p;
            t = __hadd2(*(const __half2*)&u[2*lp].x, *(const __half2*)&u[2*lp+1].x);
            p = __half22float2(t); a0.x += p.x; a0.y += p.y;
            t = __hadd2(*(const __half2*)&u[2*lp].y, *(const __half2*)&u[2*lp+1].y);
            p = __half22float2(t); a1.x += p.x; a1.y += p.y;
            t = __hadd2(*(const __half2*)&u[2*lp].z, *(const __half2*)&u[2*lp+1].z);
            p = __half22float2(t); a2.x += p.x; a2.y += p.y;
            t = __hadd2(*(const __half2*)&u[2*lp].w, *(const __half2*)&u[2*lp+1].w);
            p = __half22float2(t); a3.x += p.x; a3.y += p.y;
        }
        __half2 h0 = __floats2half2_rn(gelu_fast(a0.x), gelu_fast(a0.y));
        __half2 h1 = __floats2half2_rn(gelu_fast(a1.x), gelu_fast(a1.y));
        __half2 h2 = __floats2half2_rn(gelu_fast(a2.x), gelu_fast(a2.y));
        __half2 h3 = __floats2half2_rn(gelu_fast(a3.x), gelu_fast(a3.y));
        uint4 pk;
        pk.x = *(uint32_t*)&h0; pk.y = *(uint32_t*)&h1;
        pk.z = *(uint32_t*)&h2; pk.w = *(uint32_t*)&h3;
        const int m = it * 64 + warp * 4 + r;
        *(uint4*)(sA + buf * MSA_BUFH + m * SAH + c * 8) = pk;
    };

    auto consume2 = [&](int buf, int ks0) {
        const uint32_t aB = sbA + (uint32_t)(buf * MSA_BUFH * 2) + aoff0;
        const uint32_t bB = sbB + (uint32_t)(buf * SB_BUFH * 2) + boff0;
#pragma unroll
        for (int ks = ks0; ks < ks0 + 2; ks++) {
            uint32_t a[2][4];
#pragma unroll
            for (int mt = 0; mt < 2; mt++)
                ldsm4(a[mt][0], a[mt][1], a[mt][2], a[mt][3],
                      aB + (uint32_t)(mt * 16 * SAH * 2) + (uint32_t)(ks * 32));
#pragma unroll
            for (int jp = 0; jp < 4; jp++) {
                uint32_t b0, b1r, b2r, b3r;
                ldsm4(b0, b1r, b2r, b3r,
                      bB + (uint32_t)(jp * 16 * SBH * 2) + (uint32_t)(ks * 32));
                mma_f16(acc[0][2 * jp],     a[0], b0, b1r);
                mma_f16(acc[1][2 * jp],     a[1], b0, b1r);
                mma_f16(acc[0][2 * jp + 1], a[0], b2r, b3r);
                mma_f16(acc[1][2 * jp + 1], a[1], b2r, b3r);
            }
        }
    };

    // ---- prologue chunk 0 ----
    stageB(0, 0);
    loadA(0, 0); mathA(0, 0);
    loadA(1, 0); mathA(1, 0);
    asm volatile("cp.async.wait_group 0;" ::: "memory");
    __syncthreads();

    // ---- pipelined main loop (chunks 0..NCH-2) ----
#pragma unroll 1
    for (int kt = 0; kt < NCH - 1; kt++) {
        const int buf = kt & 1;
        loadA(0, kt + 1);          // tight-deadline gather LDGs first
        stageB(kt + 1, buf ^ 1);   // slack-rich cp.asyncs after
        consume2(buf, 0);
        mathA(0, buf ^ 1);
        loadA(1, kt + 1);
        consume2(buf, 2);
        mathA(1, buf ^ 1);
        asm volatile("cp.async.wait_group 0;" ::: "memory");
        __syncthreads();
    }
    // ---- peeled last chunk ----
    consume2((NCH - 1) & 1, 0);
    consume2((NCH - 1) & 1, 2);

    // ---- epilogue: + b2, store ----
    const float2* b2p = (const float2*)b2;
    float2* o2 = (float2*)out;
#pragma unroll
    for (int mt = 0; mt < 2; mt++) {
        size_t r0 = (size_t)blockIdx.x * MTILE + m0 + mt * 16 + (lane >> 2);
#pragma unroll
        for (int j = 0; j < 8; j++) {
            int cc = n0 / 2 + 4 * j + (lane & 3);
            float2 bv = __ldg(&b2p[cc]);
            float2 v0 = make_float2(acc[mt][j][0] + bv.x,
                                    acc[mt][j][1] + bv.y);
            float2 v1 = make_float2(acc[mt][j][2] + bv.x,
                                    acc[mt][j][3] + bv.y);
            o2[r0 * 128 + cc]       = v0;
            o2[(r0 + 8) * 128 + cc] = v1;
        }
    }
}

// ---------------------------------------------------------------------------
extern "C" void kernel_launch(void* const* d_in, const int* in_sizes, int n_in,
                              void* d_out, int out_size) {
    const unsigned int* hap    = (const unsigned int*)d_in[0];
    const float*        tables = (const float*)d_in[1];
    const float*        W1     = (const float*)d_in[2];
    const float*        b1     = (const float*)d_in[3];
    const float*        W2     = (const float*)d_in[4];
    const float*        b2     = (const float*)d_in[5];
    float*              out    = (float*)d_out;

    cudaFuncSetAttribute(gemm_p_kernel,
                         cudaFuncAttributeMaxDynamicSharedMemorySize, SMEM_BYTES);
    cudaFuncSetAttribute(main_kernel,
                         cudaFuncAttributeMaxDynamicSharedMemorySize, MSMEM_BYTES);

    convert_kernel<<<288, 256>>>(W1, W2, hap);
    gemm_p_kernel<<<128, 256, SMEM_BYTES>>>(tables, b1);
    main_kernel<<<NBLK, 512, MSMEM_BYTES>>>(hap, b2, out);
}

// round 17
// speedup vs baseline: 1.0225x; 1.0225x over previous
#include <cuda_runtime.h>
#include <cuda_fp16.h>
#include <math.h>
#include <stdint.h>

// ---------------------------------------------------------------------------
// HaplotypeEmbedding, fp16 + mma.sync m16n8k16 + ldmatrix.
// main_kernel: r15 winner EXACTLY (MTILE 64, 256 thr, occ 2, pipelined,
//              LDG-first, peeled last chunk).
// convert_kernel: 576 blocks (32x64 tiles) for DRAM-latency concurrency.
// gemm_p_kernel: r12 + peeled trailing barrier.
// ---------------------------------------------------------------------------

#define L_    8
#define V_    512
#define D_    256
#define HID_  512
#define NOUT_ 256
#define NTOT  131072
#define MTILE 64
#define NBLK  (NTOT / MTILE)   // 2048
#define KCH   64
#define NCH   (HID_ / KCH)     // 8

#define SAH 72
#define SBH 72
#define SA_BUFH (MTILE * SAH)   // 4608 halves
#define SB_BUFH (NOUT_ * SBH)   // 18432 halves

#define SM_TOK_B 0
#define SM_A_B   2048
#define SM_B_B   (SM_A_B + 2 * SA_BUFH * 2)     // 20480
#define SMEM_BYTES (SM_B_B + 2 * SB_BUFH * 2)   // 94208

__device__ __half g_Ph[L_ * V_ * HID_];      // P (+b1/8), fp16
__device__ __half g_W2T[NOUT_ * HID_];       // W2^T fp16 [n][k]
__device__ __half g_W1T[HID_ * (L_ * D_)];   // W1^T fp16 [j][d]
__device__ int    g_is64;

__device__ __forceinline__ float gelu_fast(float x) {
    float ax = fabsf(x);
    float z  = 0.70710678118f * ax;
    float t  = __fdividef(1.0f, fmaf(0.47047f, z, 1.0f));
    float q  = fmaf(fmaf(0.7478556f, t, -0.0958798f), t, 0.3480242f) * t;
    float e  = __expf(-z * z);
    float er = fmaf(-q, e, 1.0f);
    return fmaf(0.5f * ax, er, 0.5f * x);
}
__device__ __forceinline__ void mma_f16(float* d, const uint32_t* a,
                                        uint32_t b0, uint32_t b1) {
    asm volatile(
        "mma.sync.aligned.m16n8k16.row.col.f32.f16.f16.f32 "
        "{%0,%1,%2,%3}, {%4,%5,%6,%7}, {%8,%9}, {%0,%1,%2,%3};"
        : "+f"(d[0]), "+f"(d[1]), "+f"(d[2]), "+f"(d[3])
        : "r"(a[0]), "r"(a[1]), "r"(a[2]), "r"(a[3]), "r"(b0), "r"(b1));
}
__device__ __forceinline__ void ldsm4(uint32_t& r0, uint32_t& r1,
                                      uint32_t& r2, uint32_t& r3, uint32_t a) {
    asm volatile("ldmatrix.sync.aligned.m8n8.x4.shared.b16 {%0,%1,%2,%3}, [%4];"
                 : "=r"(r0), "=r"(r1), "=r"(r2), "=r"(r3) : "r"(a));
}
__device__ __forceinline__ void cpasync16(uint32_t dst, const void* src) {
    asm volatile("cp.async.ca.shared.global [%0], [%1], 16;"
                 :: "r"(dst), "l"(src) : "memory");
}

// ---------------------------------------------------------------------------
// convert: 32x64 fp32->fp16 transpose tiles. Blocks 0..511: W1 -> W1T.
// Blocks 512..575: W2 -> W2T. Block 0 thread 0: dtype detect.
__global__ void __launch_bounds__(256) convert_kernel(
        const float* __restrict__ W1, const float* __restrict__ W2,
        const unsigned int* __restrict__ hap) {
    __shared__ float sT[32 * 68];
    const int t = threadIdx.x;
    const int bx = blockIdx.x;

    if (bx == 0 && t == 0) {
        int ok = 1;
        for (int i = 0; i < 64; i++) ok &= (hap[2 * i + 1] == 0u);
        g_is64 = ok;
    }

    const float* src; __half* dst;
    int d0, j0, S, Dst;
    if (bx < 512) {         // W1 [2048 d][512 j] -> W1T [512 j][2048 d]
        d0 = (bx >> 3) * 32; j0 = (bx & 7) * 64;
        S = HID_; Dst = L_ * D_;
        src = W1; dst = g_W1T;
    } else {                // W2 [512 k][256 n] -> W2T [256 n][512 k]
        int i2 = bx - 512;
        d0 = (i2 >> 2) * 32; j0 = (i2 & 3) * 64;
        S = NOUT_; Dst = HID_;
        src = W2; dst = g_W2T;
    }

    // read 32x64 tile coalesced (8 floats / thread)
    const int rr = t >> 3, q = t & 7;
    const float* sp = src + (size_t)(d0 + rr) * S + j0 + q * 8;
    *(float4*)(sT + rr * 68 + q * 8)     = *(const float4*)(sp);
    *(float4*)(sT + rr * 68 + q * 8 + 4) = *(const float4*)(sp + 4);
    __syncthreads();

    // write transposed, fp16, coalesced (8 halves / thread)
    const int jj = t >> 2, qq = t & 3;
    __half h[8];
#pragma unroll
    for (int i = 0; i < 8; i++)
        h[i] = __float2half_rn(sT[(qq * 8 + i) * 68 + jj]);
    *(uint4*)(dst + (size_t)(j0 + jj) * Dst + d0 + qq * 8) = *(uint4*)(h);
}

// ---------------------------------------------------------------------------
__global__ void __launch_bounds__(256, 2) gemm_p_kernel(
        const float* __restrict__ tables,
        const float* __restrict__ b1) {
    extern __shared__ char smem[];
    __half* sA = (__half*)(smem + SM_A_B);
    __half* sB = (__half*)(smem + SM_B_B);
    const uint32_t sbA = (uint32_t)__cvta_generic_to_shared(sA);
    const uint32_t sbB = (uint32_t)__cvta_generic_to_shared(sB);

    const int tid = threadIdx.x, warp = tid >> 5, lane = tid & 31;
    const int l   = blockIdx.x >> 4;
    const int mv  = (blockIdx.x >> 1) & 7;
    const int nt  = blockIdx.x & 1;
    const int v0  = mv * 64;

    float acc[2][8][4];
#pragma unroll
    for (int mt = 0; mt < 2; mt++)
#pragma unroll
        for (int j = 0; j < 8; j++)
#pragma unroll
            for (int q = 0; q < 4; q++) acc[mt][j][q] = 0.f;

    const int m0 = (warp >> 2) * 32;
    const int n0 = (warp & 3) * 64;
    const int bn = tid >> 3;
    const int bc = tid & 7;
    const int ar = tid >> 2;
    const int aq = tid & 3;

    const uint32_t aoff0 = ((uint32_t)(m0 + ((lane >> 3) & 1) * 8 + (lane & 7)) * SAH +
                            (uint32_t)(lane >> 4) * 8) * 2;
    const uint32_t boff0 = ((uint32_t)(n0 + (lane >> 4) * 8 + (lane & 7)) * SBH +
                            (uint32_t)((lane >> 3) & 1) * 8) * 2;

    const float* Asrc = tables + (size_t)(l * V_ + v0 + ar) * D_ + aq * 16;
    const __half* Bsrc = g_W1T + (size_t)(nt * NOUT_) * (L_ * D_) + l * D_ + bc * 8;

    auto produce = [&](int kt, int buf) {
        {
            const uint32_t dstB = sbB + (uint32_t)(buf * SB_BUFH * 2);
#pragma unroll
            for (int i = 0; i < 8; i++) {
                int n = bn + i * 32;
                cpasync16(dstB + (uint32_t)(n * SBH + bc * 8) * 2,
                          Bsrc + (size_t)n * (L_ * D_) + kt * KCH);
            }
            asm volatile("cp.async.commit_group;" ::: "memory");
        }
        {
            const float* ap = Asrc + kt * KCH;
            __half h[16];
#pragma unroll
            for (int i = 0; i < 4; i++) {
                float4 v = *(const float4*)(ap + i * 4);
                h[4 * i + 0] = __float2half_rn(v.x);
                h[4 * i + 1] = __float2half_rn(v.y);
                h[4 * i + 2] = __float2half_rn(v.z);
                h[4 * i + 3] = __float2half_rn(v.w);
            }
            __half* A = sA + buf * SA_BUFH + ar * SAH + aq * 16;
            *(uint4*)(A)     = *(uint4*)(h);
            *(uint4*)(A + 8) = *(uint4*)(h + 8);
        }
    };

    auto consume = [&](int buf) {
        const uint32_t aB = sbA + (uint32_t)(buf * SA_BUFH * 2) + aoff0;
        const uint32_t bB = sbB + (uint32_t)(buf * SB_BUFH * 2) + boff0;
#pragma unroll
        for (int ks = 0; ks < 4; ks++) {
            uint32_t a[2][4];
#pragma unroll
            for (int mt = 0; mt < 2; mt++)
                ldsm4(a[mt][0], a[mt][1], a[mt][2], a[mt][3],
                      aB + (uint32_t)(mt * 16 * SAH * 2) + (uint32_t)(ks * 32));
#pragma unroll
            for (int jp = 0; jp < 4; jp++) {
                uint32_t b0, b1r, b2r, b3r;
                ldsm4(b0, b1r, b2r, b3r,
                      bB + (uint32_t)(jp * 16 * SBH * 2) + (uint32_t)(ks * 32));
                mma_f16(acc[0][2 * jp],     a[0], b0, b1r);
                mma_f16(acc[1][2 * jp],     a[1], b0, b1r);
                mma_f16(acc[0][2 * jp + 1], a[0], b2r, b3r);
                mma_f16(acc[1][2 * jp + 1], a[1], b2r, b3r);
            }
        }
    };

    produce(0, 0);
    asm volatile("cp.async.wait_group 0;" ::: "memory");
    __syncthreads();
#pragma unroll 1
    for (int kt = 0; kt < 3; kt++) {
        produce(kt + 1, (kt & 1) ^ 1);
        consume(kt & 1);
        asm volatile("cp.async.wait_group 0;" ::: "memory");
        __syncthreads();
    }
    consume(1);   // peeled last chunk, no trailing wait/barrier

    const float2* b1p = (const float2*)b1;
#pragma unroll
    for (int mt = 0; mt < 2; mt++) {
        int r0 = v0 + m0 + mt * 16 + (lane >> 2);
#pragma unroll
        for (int j = 0; j < 8; j++) {
            int cc = n0 / 2 + 4 * j + (lane & 3);
            int jcol = nt * NOUT_ + 2 * cc;
            float2 bv = __ldg(&b1p[jcol >> 1]);
            bv.x *= 0.125f; bv.y *= 0.125f;
            __half2 h0 = __floats2half2_rn(acc[mt][j][0] + bv.x,
                                           acc[mt][j][1] + bv.y);
            __half2 h1 = __floats2half2_rn(acc[mt][j][2] + bv.x,
                                           acc[mt][j][3] + bv.y);
            *(uint32_t*)(g_Ph + (size_t)(l * V_ + r0) * HID_ + jcol) =
                *(uint32_t*)&h0;
            *(uint32_t*)(g_Ph + (size_t)(l * V_ + r0 + 8) * HID_ + jcol) =
                *(uint32_t*)&h1;
        }
    }
}

// ---------------------------------------------------------------------------
__global__ void __launch_bounds__(256, 2) main_kernel(
        const unsigned int* __restrict__ hap,
        const float* __restrict__ b2,
        float* __restrict__ out) {
    extern __shared__ char smem[];
    int*    sTok = (int*)(smem + SM_TOK_B);
    __half* sA   = (__half*)(smem + SM_A_B);
    __half* sB   = (__half*)(smem + SM_B_B);
    const uint32_t sbA = (uint32_t)__cvta_generic_to_shared(sA);
    const uint32_t sbB = (uint32_t)__cvta_generic_to_shared(sB);

    const int tid = threadIdx.x, warp = tid >> 5, lane = tid & 31;
    const int is64 = g_is64;

    {
        long gbase = (long)blockIdx.x * (MTILE * L_);
#pragma unroll
        for (int i = 0; i < 2; i++) {
            int idx = tid + 256 * i;
            long gi = gbase + idx;
            int v = is64 ? (int)hap[2 * gi] : (int)hap[gi];
            v = v < 0 ? 0 : (v > V_ - 1 ? V_ - 1 : v);
            sTok[idx] = v;
        }
    }

    float acc[2][8][4];
#pragma unroll
    for (int mt = 0; mt < 2; mt++)
#pragma unroll
        for (int j = 0; j < 8; j++)
#pragma unroll
            for (int q = 0; q < 4; q++) acc[mt][j][q] = 0.f;

    const int c  = lane & 7;
    const int r  = lane >> 3;
    const int m0 = (warp >> 2) * 32;
    const int n0 = (warp & 3) * 64;
    const int bn = tid >> 3;
    const int bc = tid & 7;

    const uint32_t aoff0 = ((uint32_t)(m0 + ((lane >> 3) & 1) * 8 + (lane & 7)) * SAH +
                            (uint32_t)(lane >> 4) * 8) * 2;
    const uint32_t boff0 = ((uint32_t)(n0 + (lane >> 4) * 8 + (lane & 7)) * SBH +
                            (uint32_t)((lane >> 3) & 1) * 8) * 2;

    __syncthreads();

    uint4 u[8];   // gathered 16B segments for one it-half

    auto stageB = [&](int kt, int buf) {
        const uint32_t dstB = sbB + (uint32_t)(buf * SB_BUFH * 2);
        const __half* srcB = g_W2T + kt * KCH + bc * 8;
#pragma unroll
        for (int i = 0; i < 8; i++) {
            int n = bn + i * 32;
            cpasync16(dstB + (uint32_t)(n * SBH + bc * 8) * 2,
                      srcB + n * HID_);
        }
        asm volatile("cp.async.commit_group;" ::: "memory");
    };

    auto loadA = [&](int it, int kt) {
        const int k0 = kt * KCH;
        const int m = it * 32 + warp * 4 + r;
        const int* tk = sTok + m * L_;
#pragma unroll
        for (int lp = 0; lp < 8; lp++)
            u[lp] = *(const uint4*)(g_Ph +
                    ((lp * V_ + tk[lp]) << 9) + k0 + c * 8);
    };

    auto mathA = [&](int it, int buf) {
        float2 a0 = make_float2(0.f, 0.f), a1 = a0, a2 = a0, a3 = a0;
#pragma unroll
        for (int lp = 0; lp < 4; lp++) {
            __half2 t; float2 p;
            t = __hadd2(*(const __half2*)&u[2*lp].x, *(const __half2*)&u[2*lp+1].x);
            p = __half22float2(t); a0.x += p.x; a0.y += p.y;
            t = __hadd2(*(const __half2*)&u[2*lp].y, *(const __half2*)&u[2*lp+1].y);
            p = __half22float2(t); a1.x += p.x; a1.y += p.y;
            t = __hadd2(*(const __half2*)&u[2*lp].z, *(const __half2*)&u[2*lp+1].z);
            p = __half22float2(t); a2.x += p.x; a2.y += p.y;
            t = __hadd2(*(const __half2*)&u[2*lp].w, *(const __half2*)&u[2*lp+1].w);
            p = __half22float2(t); a3.x += p.x; a3.y += p.y;
        }
        __half2 h0 = __floats2half2_rn(gelu_fast(a0.x), gelu_fast(a0.y));
        __half2 h1 = __floats2half2_rn(gelu_fast(a1.x), gelu_fast(a1.y));
        __half2 h2 = __floats2half2_rn(gelu_fast(a2.x), gelu_fast(a2.y));
        __half2 h3 = __floats2half2_rn(gelu_fast(a3.x), gelu_fast(a3.y));
        uint4 pk;
        pk.x = *(uint32_t*)&h0; pk.y = *(uint32_t*)&h1;
        pk.z = *(uint32_t*)&h2; pk.w = *(uint32_t*)&h3;
        const int m = it * 32 + warp * 4 + r;
        *(uint4*)(sA + buf * SA_BUFH + m * SAH + c * 8) = pk;
    };

    auto consume2 = [&](int buf, int ks0) {
        const uint32_t aB = sbA + (uint32_t)(buf * SA_BUFH * 2) + aoff0;
        const uint32_t bB = sbB + (uint32_t)(buf * SB_BUFH * 2) + boff0;
#pragma unroll
        for (int ks = ks0; ks < ks0 + 2; ks++) {
            uint32_t a[2][4];
#pragma unroll
            for (int mt = 0; mt < 2; mt++)
                ldsm4(a[mt][0], a[mt][1], a[mt][2], a[mt][3],
                      aB + (uint32_t)(mt * 16 * SAH * 2) + (uint32_t)(ks * 32));
#pragma unroll
            for (int jp = 0; jp < 4; jp++) {
                uint32_t b0, b1r, b2r, b3r;
                ldsm4(b0, b1r, b2r, b3r,
                      bB + (uint32_t)(jp * 16 * SBH * 2) + (uint32_t)(ks * 32));
                mma_f16(acc[0][2 * jp],     a[0], b0, b1r);
                mma_f16(acc[1][2 * jp],     a[1], b0, b1r);
                mma_f16(acc[0][2 * jp + 1], a[0], b2r, b3r);
                mma_f16(acc[1][2 * jp + 1], a[1], b2r, b3r);
            }
        }
    };

    // ---- prologue chunk 0 ----
    stageB(0, 0);
    loadA(0, 0); mathA(0, 0);
    loadA(1, 0); mathA(1, 0);
    asm volatile("cp.async.wait_group 0;" ::: "memory");
    __syncthreads();

    // ---- pipelined main loop (chunks 0..NCH-2) ----
#pragma unroll 1
    for (int kt = 0; kt < NCH - 1; kt++) {
        const int buf = kt & 1;
        loadA(0, kt + 1);          // tight-deadline gather LDGs first
        stageB(kt + 1, buf ^ 1);   // slack-rich cp.asyncs after
        consume2(buf, 0);
        mathA(0, buf ^ 1);
        loadA(1, kt + 1);
        consume2(buf, 2);
        mathA(1, buf ^ 1);
        asm volatile("cp.async.wait_group 0;" ::: "memory");
        __syncthreads();
    }
    // ---- peeled last chunk ----
    consume2((NCH - 1) & 1, 0);
    consume2((NCH - 1) & 1, 2);

    // ---- epilogue: + b2, store ----
    const float2* b2p = (const float2*)b2;
    float2* o2 = (float2*)out;
#pragma unroll
    for (int mt = 0; mt < 2; mt++) {
        size_t r0 = (size_t)blockIdx.x * MTILE + m0 + mt * 16 + (lane >> 2);
#pragma unroll
        for (int j = 0; j < 8; j++) {
            int cc = n0 / 2 + 4 * j + (lane & 3);
            float2 bv = __ldg(&b2p[cc]);
            float2 v0 = make_float2(acc[mt][j][0] + bv.x,
                                    acc[mt][j][1] + bv.y);
            float2 v1 = make_float2(acc[mt][j][2] + bv.x,
                                    acc[mt][j][3] + bv.y);
            o2[r0 * 128 + cc]       = v0;
            o2[(r0 + 8) * 128 + cc] = v1;
        }
    }
}

// ---------------------------------------------------------------------------
extern "C" void kernel_launch(void* const* d_in, const int* in_sizes, int n_in,
                              void* d_out, int out_size) {
    const unsigned int* hap    = (const unsigned int*)d_in[0];
    const float*        tables = (const float*)d_in[1];
    const float*        W1     = (const float*)d_in[2];
    const float*        b1     = (const float*)d_in[3];
    const float*        W2     = (const float*)d_in[4];
    const float*        b2     = (const float*)d_in[5];
    float*              out    = (float*)d_out;

    cudaFuncSetAttribute(gemm_p_kernel,
                         cudaFuncAttributeMaxDynamicSharedMemorySize, SMEM_BYTES);
    cudaFuncSetAttribute(main_kernel,
                         cudaFuncAttributeMaxDynamicSharedMemorySize, SMEM_BYTES);

    convert_kernel<<<576, 256>>>(W1, W2, hap);
    gemm_p_kernel<<<128, 256, SMEM_BYTES>>>(tables, b1);
    main_kernel<<<NBLK, 256, SMEM_BYTES>>>(hap, b2, out);
}